// round 16
// baseline (speedup 1.0000x reference)
#include <cuda_runtime.h>
#include <cuda_bf16.h>
#include <math.h>
#include <stdint.h>

// ---------------------------------------------------------------------------
// Problem constants
// ---------------------------------------------------------------------------
#define BATCH    8
#define NPTS     4096
#define WIDTH    768
#define HEADS    12
#define LAYERS   8
#define N_LAT    256
#define D_HEAD   64
#define IN_DIM   54
#define BN_ROWS  (BATCH * NPTS)        // 32768
#define LAT_ROWS (BATCH * N_LAT)       // 2048

#define FLAG_RES    1
#define FLAG_GELU   2
#define FLAG_NOBIAS 4

// ---------------------------------------------------------------------------
// Scratch (device globals; no allocation allowed)
// ---------------------------------------------------------------------------
__device__ float g_data[BN_ROWS * WIDTH];
__device__ float g_kv  [BN_ROWS * 2 * WIDTH];
__device__ float g_q   [N_LAT * WIDTH];
__device__ float g_attn[LAT_ROWS * WIDTH];
__device__ float g_x   [LAT_ROWS * WIDTH];
__device__ float g_h   [LAT_ROWS * WIDTH];
__device__ float g_ffn [LAT_ROWS * 4 * WIDTH];
__device__ float g_split[2 * LAT_ROWS * WIDTH];   // split-K partials

// tf32-rounded weights, one big arena (contiguous regions)
#define W_CAQKV   0L
#define W_CAPROJ  1769472L
#define W_QKV     2359296L
#define W_PROJ    16515072L
#define W_FC      21233664L
#define W_FC2     40108032L
#define W_TOTAL   58982400L
__device__ float g_wtf[W_TOTAL];

// ---------------------------------------------------------------------------
// Helpers (sm_80+ features only — NO tcgen05; bench targets plain sm_103)
// ---------------------------------------------------------------------------
__device__ __forceinline__ uint32_t smem_u32(const void* p) {
    uint32_t a;
    asm("{ .reg .u64 t; cvta.to.shared.u64 t, %1; cvt.u32.u64 %0, t; }"
        : "=r"(a) : "l"(p));
    return a;
}
__device__ __forceinline__ void cp16(uint32_t dst, const void* src) {
    asm volatile("cp.async.cg.shared.global [%0], [%1], 16;"
                 :: "r"(dst), "l"(src) : "memory");
}
__device__ __forceinline__ float rna_f(float x) {
    uint32_t u;
    asm("cvt.rna.tf32.f32 %0, %1;" : "=r"(u) : "f"(x));
    return __uint_as_float(u);
}
__device__ __forceinline__ void mma1688(float* c, const uint32_t* a,
                                        uint32_t b0, uint32_t b1) {
    asm volatile(
        "mma.sync.aligned.m16n8k8.row.col.f32.tf32.tf32.f32 "
        "{%0,%1,%2,%3},{%4,%5,%6,%7},{%8,%9},{%0,%1,%2,%3};"
        : "+f"(c[0]), "+f"(c[1]), "+f"(c[2]), "+f"(c[3])
        : "r"(a[0]), "r"(a[1]), "r"(a[2]), "r"(a[3]), "r"(b0), "r"(b1));
}

// ---------------------------------------------------------------------------
// Fused rna tf32 rounding of ALL weights (single launch); units are float4
// ---------------------------------------------------------------------------
#define R4_E0 442368L
#define R4_E1 589824L
#define R4_E2 4128768L
#define R4_E3 5308416L
#define R4_E4 10027008L
#define R4_E5 14745600L

__global__ void rna_all(const float* __restrict__ s0, const float* __restrict__ s1,
                        const float* __restrict__ s2, const float* __restrict__ s3,
                        const float* __restrict__ s4, const float* __restrict__ s5,
                        float4* __restrict__ dst)
{
    long i = (long)blockIdx.x * 256 + threadIdx.x;
    if (i >= R4_E5) return;
    const float4* src; long off;
    if (i < R4_E0)      { src = (const float4*)s0; off = i; }
    else if (i < R4_E1) { src = (const float4*)s1; off = i - R4_E0; }
    else if (i < R4_E2) { src = (const float4*)s2; off = i - R4_E1; }
    else if (i < R4_E3) { src = (const float4*)s3; off = i - R4_E2; }
    else if (i < R4_E4) { src = (const float4*)s4; off = i - R4_E3; }
    else                { src = (const float4*)s5; off = i - R4_E4; }
    float4 v = src[off];
    v.x = rna_f(v.x); v.y = rna_f(v.y); v.z = rna_f(v.z); v.w = rna_f(v.w);
    dst[i] = v;
}

// ---------------------------------------------------------------------------
// tf32 mma.sync GEMM: C[M,N] = A[M,K] @ B[N,K]^T + bias (+res)(gelu+rna)
// CTA 128x128, BK=32, 3-stage cp.async, one barrier per k-tile, 8 warps.
// K = loop extent; ldk = row stride. gridDim.z>1 => split-K: z picks the
// K-slice (offset z*K into rows) and output slab C + z*M*N.
// ---------------------------------------------------------------------------
#define NSTG 3
#define STRIDE 36
#define STAGE_BYTES (128 * STRIDE * 4)           // 18432
#define GEMM_SMEM (2 * NSTG * STAGE_BYTES)       // 110592

__device__ __forceinline__ void load_stage(uint32_t abase, uint32_t bbase,
                                           const float* __restrict__ A,
                                           const float* __restrict__ B,
                                           int ldk, int cm, int cn, int kt, int tid)
{
    const float* Ak = A + (long)cm * ldk + kt * 32;
    const float* Bk = B + (long)cn * ldk + kt * 32;
    #pragma unroll
    for (int it = 0; it < 4; ++it) {
        int i = tid + it * 256;
        int r = i >> 3, c = i & 7;
        cp16(abase + r * (STRIDE * 4) + c * 16, Ak + (long)r * ldk + c * 4);
    }
    #pragma unroll
    for (int it = 0; it < 4; ++it) {
        int i = tid + it * 256;
        int r = i >> 3, c = i & 7;
        cp16(bbase + r * (STRIDE * 4) + c * 16, Bk + (long)r * ldk + c * 4);
    }
}

__global__ __launch_bounds__(256, 2)
void gemm_mma(const float* __restrict__ A, const float* __restrict__ Bw,
              const float* __restrict__ bias, const float* __restrict__ Res,
              float* __restrict__ C, int M, int N, int K, int ldk, int flags)
{
    extern __shared__ char smem[];
    const uint32_t sb = smem_u32(smem);

    const int tid = threadIdx.x;
    const int lane = tid & 31;
    const int wid = tid >> 5;
    const int warpM = wid & 3;        // 4 warps along M (32 rows each)
    const int warpN = wid >> 2;       // 2 warps along N (64 cols each)
    const int cm = blockIdx.y * 128;
    const int cn = blockIdx.x * 128;

    // split-K offsets
    A  += (long)blockIdx.z * K;
    Bw += (long)blockIdx.z * K;
    C  += (long)blockIdx.z * (long)M * N;

    float acc[2][8][4];
    #pragma unroll
    for (int mi = 0; mi < 2; ++mi)
        #pragma unroll
        for (int ni = 0; ni < 8; ++ni)
            #pragma unroll
            for (int j = 0; j < 4; ++j) acc[mi][ni][j] = 0.f;

    const int KT = K >> 5;
    #pragma unroll
    for (int p = 0; p < NSTG - 1; ++p) {
        load_stage(sb + p * STAGE_BYTES, sb + (NSTG + p) * STAGE_BYTES,
                   A, Bw, ldk, cm, cn, p, tid);
        asm volatile("cp.async.commit_group;" ::: "memory");
    }

    const int la = lane >> 2;
    const int lk = lane & 3;

    for (int kt = 0; kt < KT; ++kt) {
        const int s = kt % NSTG;
        asm volatile("cp.async.wait_group 1;" ::: "memory");
        __syncthreads();

        {
            const int kn = kt + NSTG - 1;
            if (kn < KT) {
                const int sn = kn % NSTG;
                load_stage(sb + sn * STAGE_BYTES, sb + (NSTG + sn) * STAGE_BYTES,
                           A, Bw, ldk, cm, cn, kn, tid);
            }
            asm volatile("cp.async.commit_group;" ::: "memory");
        }

        const uint32_t* As = (const uint32_t*)(smem + s * STAGE_BYTES);
        const uint32_t* Bs = (const uint32_t*)(smem + (NSTG + s) * STAGE_BYTES);
        #pragma unroll
        for (int ks = 0; ks < 4; ++ks) {
            const int k0 = ks * 8 + lk;
            uint32_t a[2][4];
            #pragma unroll
            for (int mi = 0; mi < 2; ++mi) {
                const int r = warpM * 32 + mi * 16 + la;
                a[mi][0] = As[r * STRIDE + k0];
                a[mi][1] = As[(r + 8) * STRIDE + k0];
                a[mi][2] = As[r * STRIDE + k0 + 4];
                a[mi][3] = As[(r + 8) * STRIDE + k0 + 4];
            }
            #pragma unroll
            for (int ni = 0; ni < 8; ++ni) {
                const int n = warpN * 64 + ni * 8 + la;
                const uint32_t b0 = Bs[n * STRIDE + k0];
                const uint32_t b1 = Bs[n * STRIDE + k0 + 4];
                mma1688(acc[0][ni], a[0], b0, b1);
                mma1688(acc[1][ni], a[1], b0, b1);
            }
        }
    }

    #pragma unroll
    for (int mi = 0; mi < 2; ++mi) {
        #pragma unroll
        for (int half = 0; half < 2; ++half) {
            const int row = cm + warpM * 32 + mi * 16 + la + half * 8;
            const long rb = (long)row * N;
            #pragma unroll
            for (int ni = 0; ni < 8; ++ni) {
                const int c = cn + warpN * 64 + ni * 8 + lk * 2;
                float v0 = acc[mi][ni][half * 2 + 0];
                float v1 = acc[mi][ni][half * 2 + 1];
                if (!(flags & FLAG_NOBIAS)) {
                    v0 += bias[c]; v1 += bias[c + 1];
                }
                if (flags & FLAG_GELU) {
                    v0 = 0.5f * v0 * (1.0f + erff(v0 * 0.70710678118654752f));
                    v1 = 0.5f * v1 * (1.0f + erff(v1 * 0.70710678118654752f));
                    v0 = rna_f(v0);
                    v1 = rna_f(v1);
                }
                if (flags & FLAG_RES) {
                    float2 r = *(const float2*)&Res[rb + c];
                    v0 += r.x; v1 += r.y;
                }
                float2 o; o.x = v0; o.y = v1;
                *(float2*)&C[rb + c] = o;
            }
        }
    }
}

// ---------------------------------------------------------------------------
// add3: out = s1 + s2 + bias (+res)   (split-K reduction)
// ---------------------------------------------------------------------------
__global__ void add3_kernel(const float4* __restrict__ s1, const float4* __restrict__ s2,
                            const float4* __restrict__ res, const float* __restrict__ bias,
                            float4* __restrict__ out, int Ncols, int n4, int useRes)
{
    int i = blockIdx.x * 256 + threadIdx.x;
    if (i >= n4) return;
    float4 a = s1[i], b = s2[i];
    int col = (i * 4) % Ncols;
    float4 v;
    v.x = a.x + b.x + bias[col];
    v.y = a.y + b.y + bias[col + 1];
    v.z = a.z + b.z + bias[col + 2];
    v.w = a.w + b.w + bias[col + 3];
    if (useRes) {
        float4 r = res[i];
        v.x += r.x; v.y += r.y; v.z += r.z; v.w += r.w;
    }
    out[i] = v;
}

// ---------------------------------------------------------------------------
// Fourier embed + input projection (rna output: feeds kv GEMM)
// ---------------------------------------------------------------------------
__global__ void embed_kernel(const float* __restrict__ pc,
                             const float* __restrict__ feats,
                             const float* __restrict__ inW,
                             const float* __restrict__ inb,
                             float* __restrict__ out)
{
    __shared__ float e[IN_DIM];
    const int row = blockIdx.x;
    const int t = threadIdx.x;
    if (t < IN_DIM) {
        float v;
        if (t < 3) {
            v = pc[row * 3 + t];
        } else if (t < 27) {
            int j = (t - 3) >> 3, f = (t - 3) & 7;
            v = sinf(pc[row * 3 + j] * (float)(1 << f));
        } else if (t < 51) {
            int j = (t - 27) >> 3, f = (t - 27) & 7;
            v = cosf(pc[row * 3 + j] * (float)(1 << f));
        } else {
            v = feats[row * 3 + (t - 51)];
        }
        e[t] = v;
    }
    __syncthreads();
    #pragma unroll
    for (int rep = 0; rep < 3; ++rep) {
        int o = t + rep * 256;
        const float* w = inW + o * IN_DIM;
        float s = inb[o];
        #pragma unroll
        for (int k = 0; k < IN_DIM; ++k) s = fmaf(w[k], e[k], s);
        out[(long)row * WIDTH + o] = rna_f(s);
    }
}

// ---------------------------------------------------------------------------
// LayerNorm (rna output: feeds qkv / fc GEMMs)
// ---------------------------------------------------------------------------
__global__ void ln_kernel(const float* __restrict__ X,
                          const float* __restrict__ s,
                          const float* __restrict__ b,
                          float* __restrict__ Y)
{
    const int row = blockIdx.x;
    const int t = threadIdx.x;
    const float* x = X + (long)row * WIDTH;
    float v0 = x[t], v1 = x[t + 256], v2 = x[t + 512];
    float sum = v0 + v1 + v2;
    float sq = v0 * v0 + v1 * v1 + v2 * v2;
    __shared__ float red[16];
    #pragma unroll
    for (int o = 16; o; o >>= 1) {
        sum += __shfl_xor_sync(0xffffffffu, sum, o);
        sq  += __shfl_xor_sync(0xffffffffu, sq,  o);
    }
    const int w = t >> 5, l = t & 31;
    if (l == 0) { red[w] = sum; red[w + 8] = sq; }
    __syncthreads();
    if (t < 32) {
        float a = (l < 8) ? red[l] : 0.f;
        float c = (l < 8) ? red[l + 8] : 0.f;
        #pragma unroll
        for (int o = 4; o; o >>= 1) {
            a += __shfl_xor_sync(0xffffffffu, a, o);
            c += __shfl_xor_sync(0xffffffffu, c, o);
        }
        if (l == 0) { red[0] = a; red[1] = c; }
    }
    __syncthreads();
    const float mu = red[0] * (1.f / WIDTH);
    const float var = red[1] * (1.f / WIDTH) - mu * mu;
    const float rs = rsqrtf(var + 1e-5f);
    float* y = Y + (long)row * WIDTH;
    y[t]       = rna_f((v0 - mu) * rs * s[t]       + b[t]);
    y[t + 256] = rna_f((v1 - mu) * rs * s[t + 256] + b[t + 256]);
    y[t + 512] = rna_f((v2 - mu) * rs * s[t + 512] + b[t + 512]);
}

// ---------------------------------------------------------------------------
// Flash attention fp32 SIMT (R13 version — measured best; rna output)
// ---------------------------------------------------------------------------
#define FLASH_SMEM ((2 * 128 * 65 + 2 * 64 * 65) * 4)

__global__ __launch_bounds__(256)
void flash_kernel(const float* __restrict__ Qp, const float* __restrict__ Kp,
                  const float* __restrict__ Vp, float* __restrict__ Op,
                  int Lk, int qRS, int kRS, int oRS,
                  long qBS, long kBS, long oBS,
                  int qHS, int kHS, int oHS)
{
    extern __shared__ float sm[];
    float* Qs = sm;
    float* Ps = sm + 128 * 65;
    float* Ks = sm + 2 * 128 * 65;
    float* Vs = Ks + 64 * 65;

    const int tid = threadIdx.x;
    const int tx = tid & 15;
    const int ty = tid >> 4;
    const int qt = blockIdx.x, h = blockIdx.y, b = blockIdx.z;

    const float* Q  = Qp + (long)b * qBS + h * qHS + (long)(qt * 128) * qRS;
    const float* Kb = Kp + (long)b * kBS + h * kHS;
    const float* Vb = Vp + (long)b * kBS + h * kHS;
    float*       O  = Op + (long)b * oBS + h * oHS + (long)(qt * 128) * oRS;

    for (int idx = tid; idx < 128 * 64; idx += 256) {
        int r = idx >> 6, d = idx & 63;
        Qs[r * 65 + d] = Q[(long)r * qRS + d];
    }

    float m[8], l[8], o[8][4];
    #pragma unroll
    for (int i = 0; i < 8; ++i) {
        m[i] = -3.0e38f; l[i] = 0.f;
        #pragma unroll
        for (int j = 0; j < 4; ++j) o[i][j] = 0.f;
    }
    __syncthreads();

    for (int c0 = 0; c0 < Lk; c0 += 64) {
        for (int idx = tid; idx < 64 * 64; idx += 256) {
            int r = idx >> 6, d = idx & 63;
            Ks[r * 65 + d] = Kb[(long)(c0 + r) * kRS + d];
            Vs[r * 65 + d] = Vb[(long)(c0 + r) * kRS + d];
        }
        __syncthreads();

        float s[8][4];
        #pragma unroll
        for (int i = 0; i < 8; ++i)
            #pragma unroll
            for (int j = 0; j < 4; ++j) s[i][j] = 0.f;
        #pragma unroll 16
        for (int d = 0; d < 64; ++d) {
            float a[8], bf[4];
            #pragma unroll
            for (int i = 0; i < 8; ++i) a[i] = Qs[(ty * 8 + i) * 65 + d];
            #pragma unroll
            for (int j = 0; j < 4; ++j) bf[j] = Ks[(tx * 4 + j) * 65 + d];
            #pragma unroll
            for (int i = 0; i < 8; ++i)
                #pragma unroll
                for (int j = 0; j < 4; ++j)
                    s[i][j] = fmaf(a[i], bf[j], s[i][j]);
        }

        #pragma unroll
        for (int i = 0; i < 8; ++i) {
            #pragma unroll
            for (int j = 0; j < 4; ++j) s[i][j] *= 0.125f;
            float mx = fmaxf(fmaxf(s[i][0], s[i][1]), fmaxf(s[i][2], s[i][3]));
            #pragma unroll
            for (int off = 1; off < 16; off <<= 1)
                mx = fmaxf(mx, __shfl_xor_sync(0xffffffffu, mx, off));
            const float mnew = fmaxf(m[i], mx);
            const float corr = __expf(m[i] - mnew);
            m[i] = mnew;
            float rsum = 0.f;
            #pragma unroll
            for (int j = 0; j < 4; ++j) {
                s[i][j] = __expf(s[i][j] - mnew);
                rsum += s[i][j];
            }
            #pragma unroll
            for (int off = 1; off < 16; off <<= 1)
                rsum += __shfl_xor_sync(0xffffffffu, rsum, off);
            l[i] = l[i] * corr + rsum;
            #pragma unroll
            for (int j = 0; j < 4; ++j) {
                o[i][j] *= corr;
                Ps[(ty * 8 + i) * 65 + tx * 4 + j] = s[i][j];
            }
        }
        __syncthreads();

        #pragma unroll 16
        for (int c = 0; c < 64; ++c) {
            float a[8], bf[4];
            #pragma unroll
            for (int i = 0; i < 8; ++i) a[i] = Ps[(ty * 8 + i) * 65 + c];
            #pragma unroll
            for (int j = 0; j < 4; ++j) bf[j] = Vs[c * 65 + tx * 4 + j];
            #pragma unroll
            for (int i = 0; i < 8; ++i)
                #pragma unroll
                for (int j = 0; j < 4; ++j)
                    o[i][j] = fmaf(a[i], bf[j], o[i][j]);
        }
        __syncthreads();
    }

    #pragma unroll
    for (int i = 0; i < 8; ++i) {
        const float inv = 1.f / l[i];
        const int r = ty * 8 + i;
        #pragma unroll
        for (int j = 0; j < 4; ++j)
            O[(long)r * oRS + tx * 4 + j] = rna_f(o[i][j] * inv);
    }
}

__global__ void copy_kernel(const float* __restrict__ src, float* __restrict__ dst, int n)
{
    int i = blockIdx.x * 256 + threadIdx.x;
    if (i < n) dst[i] = src[i];
}

// ---------------------------------------------------------------------------
// kernel_launch
// ---------------------------------------------------------------------------
extern "C" void kernel_launch(void* const* d_in, const int* in_sizes, int n_in,
                              void* d_out, int out_size)
{
    const float* pc       = (const float*)d_in[0];
    const float* feats    = (const float*)d_in[1];
    const float* query    = (const float*)d_in[2];
    const float* in_W     = (const float*)d_in[3];
    const float* in_b     = (const float*)d_in[4];
    const float* ca_qkv_W = (const float*)d_in[5];
    const float* ca_qkv_b = (const float*)d_in[6];
    const float* ca_proj_W= (const float*)d_in[7];
    const float* ca_proj_b= (const float*)d_in[8];
    const float* ln1_s    = (const float*)d_in[9];
    const float* ln1_b    = (const float*)d_in[10];
    const float* qkv_W    = (const float*)d_in[11];
    const float* qkv_b    = (const float*)d_in[12];
    const float* proj_W   = (const float*)d_in[13];
    const float* proj_b   = (const float*)d_in[14];
    const float* ln2_s    = (const float*)d_in[15];
    const float* ln2_b    = (const float*)d_in[16];
    const float* fc_W     = (const float*)d_in[17];
    const float* fc_b     = (const float*)d_in[18];
    const float* fc2_W    = (const float*)d_in[19];
    const float* fc2_b    = (const float*)d_in[20];

    float *data, *kv, *qb, *attn, *x, *h, *ffn, *wtf, *split;
    cudaGetSymbolAddress((void**)&data, g_data);
    cudaGetSymbolAddress((void**)&kv,   g_kv);
    cudaGetSymbolAddress((void**)&qb,   g_q);
    cudaGetSymbolAddress((void**)&attn, g_attn);
    cudaGetSymbolAddress((void**)&x,    g_x);
    cudaGetSymbolAddress((void**)&h,    g_h);
    cudaGetSymbolAddress((void**)&ffn,  g_ffn);
    cudaGetSymbolAddress((void**)&wtf,  g_wtf);
    cudaGetSymbolAddress((void**)&split, g_split);

    cudaFuncSetAttribute(flash_kernel, cudaFuncAttributeMaxDynamicSharedMemorySize,
                         FLASH_SMEM);
    cudaFuncSetAttribute(gemm_mma, cudaFuncAttributeMaxDynamicSharedMemorySize,
                         GEMM_SMEM);

    const int n4 = LAT_ROWS * WIDTH / 4;
    const int add_blocks = (n4 + 255) / 256;

    // 0) round all weights to tf32 (single fused launch)
    rna_all<<<(int)((R4_E5 + 255) / 256), 256>>>(
        ca_qkv_W, ca_proj_W, qkv_W, proj_W, fc_W, fc2_W, (float4*)wtf);

    // 1) fourier embed + input projection
    embed_kernel<<<BN_ROWS, 256>>>(pc, feats, in_W, in_b, data);

    // 2) kv = data @ ca_qkv_W[768:2304].T + b[768:]
    gemm_mma<<<dim3((2 * WIDTH) / 128, BN_ROWS / 128), 256, GEMM_SMEM>>>(
        data, wtf + W_CAQKV + (long)WIDTH * WIDTH, ca_qkv_b + WIDTH, nullptr, kv,
        BN_ROWS, 2 * WIDTH, WIDTH, WIDTH, 0);

    // 3) q = query @ ca_qkv_W[:768].T + b[:768]
    gemm_mma<<<dim3(WIDTH / 128, N_LAT / 128), 256, GEMM_SMEM>>>(
        query, wtf + W_CAQKV, ca_qkv_b, nullptr, qb, N_LAT, WIDTH, WIDTH, WIDTH, 0);

    // 4) cross attention (latents attend to 4096 points)
    flash_kernel<<<dim3(N_LAT / 128, HEADS, BATCH), 256, FLASH_SMEM>>>(
        qb, kv, kv + WIDTH, attn,
        NPTS, WIDTH, 2 * WIDTH, WIDTH,
        0L, (long)NPTS * 2 * WIDTH, (long)N_LAT * WIDTH,
        D_HEAD, D_HEAD, D_HEAD);

    // 5) latents = attn @ ca_proj_W.T + b   (split-K x2)
    gemm_mma<<<dim3(WIDTH / 128, LAT_ROWS / 128, 2), 256, GEMM_SMEM>>>(
        attn, wtf + W_CAPROJ, nullptr, nullptr, split,
        LAT_ROWS, WIDTH, WIDTH / 2, WIDTH, FLAG_NOBIAS);
    add3_kernel<<<add_blocks, 256>>>(
        (const float4*)split, (const float4*)(split + (long)LAT_ROWS * WIDTH),
        nullptr, ca_proj_b, (float4*)x, WIDTH, n4, 0);

    // 6) transformer blocks
    for (int L = 0; L < LAYERS; ++L) {
        ln_kernel<<<LAT_ROWS, 256>>>(x, ln1_s + L * WIDTH, ln1_b + L * WIDTH, h);

        float* qkvb = ffn;
        gemm_mma<<<dim3((3 * WIDTH) / 128, LAT_ROWS / 128), 256, GEMM_SMEM>>>(
            h, wtf + W_QKV + (long)L * 3 * WIDTH * WIDTH, qkv_b + (long)L * 3 * WIDTH,
            nullptr, qkvb, LAT_ROWS, 3 * WIDTH, WIDTH, WIDTH, 0);

        flash_kernel<<<dim3(N_LAT / 128, HEADS, BATCH), 256, FLASH_SMEM>>>(
            qkvb, qkvb + D_HEAD, qkvb + 2 * D_HEAD, attn,
            N_LAT, 3 * WIDTH, 3 * WIDTH, WIDTH,
            (long)N_LAT * 3 * WIDTH, (long)N_LAT * 3 * WIDTH, (long)N_LAT * WIDTH,
            3 * D_HEAD, 3 * D_HEAD, D_HEAD);

        // proj: split-K x2 + add (res = x)
        gemm_mma<<<dim3(WIDTH / 128, LAT_ROWS / 128, 2), 256, GEMM_SMEM>>>(
            attn, wtf + W_PROJ + (long)L * WIDTH * WIDTH, nullptr, nullptr, split,
            LAT_ROWS, WIDTH, WIDTH / 2, WIDTH, FLAG_NOBIAS);
        add3_kernel<<<add_blocks, 256>>>(
            (const float4*)split, (const float4*)(split + (long)LAT_ROWS * WIDTH),
            (const float4*)x, proj_b + (long)L * WIDTH, (float4*)x, WIDTH, n4, 1);

        ln_kernel<<<LAT_ROWS, 256>>>(x, ln2_s + L * WIDTH, ln2_b + L * WIDTH, h);

        gemm_mma<<<dim3((4 * WIDTH) / 128, LAT_ROWS / 128), 256, GEMM_SMEM>>>(
            h, wtf + W_FC + (long)L * 4 * WIDTH * WIDTH, fc_b + (long)L * 4 * WIDTH,
            nullptr, ffn, LAT_ROWS, 4 * WIDTH, WIDTH, WIDTH, FLAG_GELU);

        // fc2: split-K x2 + add (res = x)
        float* Cout = (L == LAYERS - 1) ? (float*)d_out : x;
        gemm_mma<<<dim3(WIDTH / 128, LAT_ROWS / 128, 2), 256, GEMM_SMEM>>>(
            ffn, wtf + W_FC2 + (long)L * WIDTH * 4 * WIDTH, nullptr, nullptr, split,
            LAT_ROWS, WIDTH, 2 * WIDTH, 4 * WIDTH, FLAG_NOBIAS);
        add3_kernel<<<add_blocks, 256>>>(
            (const float4*)split, (const float4*)(split + (long)LAT_ROWS * WIDTH),
            (const float4*)x, fc2_b + (long)L * WIDTH, (float4*)Cout, WIDTH, n4, 1);
    }

    // 7) pc passthrough if output holds both
    const int lat_elems = LAT_ROWS * WIDTH;
    const int pc_elems = BATCH * NPTS * 3;
    if (out_size >= lat_elems + pc_elems) {
        copy_kernel<<<(pc_elems + 255) / 256, 256>>>(
            pc, (float*)d_out + lat_elems, pc_elems);
    }
}

// round 17
// speedup vs baseline: 1.5834x; 1.5834x over previous
#include <cuda_runtime.h>
#include <cuda_bf16.h>
#include <math.h>
#include <stdint.h>

// ---------------------------------------------------------------------------
// Problem constants
// ---------------------------------------------------------------------------
#define BATCH    8
#define NPTS     4096
#define WIDTH    768
#define HEADS    12
#define LAYERS   8
#define N_LAT    256
#define D_HEAD   64
#define IN_DIM   54
#define BN_ROWS  (BATCH * NPTS)        // 32768
#define LAT_ROWS (BATCH * N_LAT)       // 2048

#define FLAG_RES    1
#define FLAG_GELU   2
#define FLAG_NOBIAS 4

// ---------------------------------------------------------------------------
// Scratch (device globals; no allocation allowed)
// ---------------------------------------------------------------------------
__device__ float g_data[BN_ROWS * WIDTH];
__device__ float g_kv  [BN_ROWS * 2 * WIDTH];
__device__ float g_q   [N_LAT * WIDTH];
__device__ float g_attn[LAT_ROWS * WIDTH];
__device__ float g_x   [LAT_ROWS * WIDTH];
__device__ float g_h   [LAT_ROWS * WIDTH];
__device__ float g_ffn [LAT_ROWS * 4 * WIDTH];
__device__ float g_split[2 * LAT_ROWS * WIDTH];   // split-K partials

// tf32-rounded weights, one big arena (contiguous regions)
#define W_CAQKV   0L
#define W_CAPROJ  1769472L
#define W_QKV     2359296L
#define W_PROJ    16515072L
#define W_FC      21233664L
#define W_FC2     40108032L
#define W_TOTAL   58982400L
__device__ float g_wtf[W_TOTAL];

// ---------------------------------------------------------------------------
// Helpers (sm_80+ features only — NO tcgen05; bench targets plain sm_103)
// ---------------------------------------------------------------------------
__device__ __forceinline__ uint32_t smem_u32(const void* p) {
    uint32_t a;
    asm("{ .reg .u64 t; cvta.to.shared.u64 t, %1; cvt.u32.u64 %0, t; }"
        : "=r"(a) : "l"(p));
    return a;
}
__device__ __forceinline__ void cp16(uint32_t dst, const void* src) {
    asm volatile("cp.async.cg.shared.global [%0], [%1], 16;"
                 :: "r"(dst), "l"(src) : "memory");
}
__device__ __forceinline__ float rna_f(float x) {
    uint32_t u;
    asm("cvt.rna.tf32.f32 %0, %1;" : "=r"(u) : "f"(x));
    return __uint_as_float(u);
}
__device__ __forceinline__ void mma1688(float* c, const uint32_t* a,
                                        uint32_t b0, uint32_t b1) {
    asm volatile(
        "mma.sync.aligned.m16n8k8.row.col.f32.tf32.tf32.f32 "
        "{%0,%1,%2,%3},{%4,%5,%6,%7},{%8,%9},{%0,%1,%2,%3};"
        : "+f"(c[0]), "+f"(c[1]), "+f"(c[2]), "+f"(c[3])
        : "r"(a[0]), "r"(a[1]), "r"(a[2]), "r"(a[3]), "r"(b0), "r"(b1));
}

// ---------------------------------------------------------------------------
// Fused rna tf32 rounding of ALL weights (single launch); units are float4
// ---------------------------------------------------------------------------
#define R4_E0 442368L
#define R4_E1 589824L
#define R4_E2 4128768L
#define R4_E3 5308416L
#define R4_E4 10027008L
#define R4_E5 14745600L

__global__ void rna_all(const float* __restrict__ s0, const float* __restrict__ s1,
                        const float* __restrict__ s2, const float* __restrict__ s3,
                        const float* __restrict__ s4, const float* __restrict__ s5,
                        float4* __restrict__ dst)
{
    long i = (long)blockIdx.x * 256 + threadIdx.x;
    if (i >= R4_E5) return;
    const float4* src; long off;
    if (i < R4_E0)      { src = (const float4*)s0; off = i; }
    else if (i < R4_E1) { src = (const float4*)s1; off = i - R4_E0; }
    else if (i < R4_E2) { src = (const float4*)s2; off = i - R4_E1; }
    else if (i < R4_E3) { src = (const float4*)s3; off = i - R4_E2; }
    else if (i < R4_E4) { src = (const float4*)s4; off = i - R4_E3; }
    else                { src = (const float4*)s5; off = i - R4_E4; }
    float4 v = src[off];
    v.x = rna_f(v.x); v.y = rna_f(v.y); v.z = rna_f(v.z); v.w = rna_f(v.w);
    dst[i] = v;
}

// ---------------------------------------------------------------------------
// tf32 mma.sync GEMM: C[M,N] = A[M,K] @ B[N,K]^T + bias (+res)(gelu+rna)
// CTA 128x128, BK=32, 3-stage cp.async, one barrier per k-tile, 8 warps.
// K = loop extent; ldk = row stride. gridDim.z>1 => split-K: z picks the
// K-slice (offset z*K into rows) and output slab C + z*M*N.
// ---------------------------------------------------------------------------
#define NSTG 3
#define STRIDE 36
#define STAGE_BYTES (128 * STRIDE * 4)           // 18432
#define GEMM_SMEM (2 * NSTG * STAGE_BYTES)       // 110592

__device__ __forceinline__ void load_stage(uint32_t abase, uint32_t bbase,
                                           const float* __restrict__ A,
                                           const float* __restrict__ B,
                                           int ldk, int cm, int cn, int kt, int tid)
{
    const float* Ak = A + (long)cm * ldk + kt * 32;
    const float* Bk = B + (long)cn * ldk + kt * 32;
    #pragma unroll
    for (int it = 0; it < 4; ++it) {
        int i = tid + it * 256;
        int r = i >> 3, c = i & 7;
        cp16(abase + r * (STRIDE * 4) + c * 16, Ak + (long)r * ldk + c * 4);
    }
    #pragma unroll
    for (int it = 0; it < 4; ++it) {
        int i = tid + it * 256;
        int r = i >> 3, c = i & 7;
        cp16(bbase + r * (STRIDE * 4) + c * 16, Bk + (long)r * ldk + c * 4);
    }
}

__global__ __launch_bounds__(256, 2)
void gemm_mma(const float* __restrict__ A, const float* __restrict__ Bw,
              const float* __restrict__ bias, const float* __restrict__ Res,
              float* __restrict__ C, int M, int N, int K, int ldk, int flags)
{
    extern __shared__ char smem[];
    const uint32_t sb = smem_u32(smem);

    const int tid = threadIdx.x;
    const int lane = tid & 31;
    const int wid = tid >> 5;
    const int warpM = wid & 3;        // 4 warps along M (32 rows each)
    const int warpN = wid >> 2;       // 2 warps along N (64 cols each)
    const int cm = blockIdx.y * 128;
    const int cn = blockIdx.x * 128;

    // split-K offsets
    A  += (long)blockIdx.z * K;
    Bw += (long)blockIdx.z * K;
    C  += (long)blockIdx.z * (long)M * N;

    float acc[2][8][4];
    #pragma unroll
    for (int mi = 0; mi < 2; ++mi)
        #pragma unroll
        for (int ni = 0; ni < 8; ++ni)
            #pragma unroll
            for (int j = 0; j < 4; ++j) acc[mi][ni][j] = 0.f;

    const int KT = K >> 5;
    #pragma unroll
    for (int p = 0; p < NSTG - 1; ++p) {
        load_stage(sb + p * STAGE_BYTES, sb + (NSTG + p) * STAGE_BYTES,
                   A, Bw, ldk, cm, cn, p, tid);
        asm volatile("cp.async.commit_group;" ::: "memory");
    }

    const int la = lane >> 2;
    const int lk = lane & 3;

    for (int kt = 0; kt < KT; ++kt) {
        const int s = kt % NSTG;
        asm volatile("cp.async.wait_group 1;" ::: "memory");
        __syncthreads();

        {
            const int kn = kt + NSTG - 1;
            if (kn < KT) {
                const int sn = kn % NSTG;
                load_stage(sb + sn * STAGE_BYTES, sb + (NSTG + sn) * STAGE_BYTES,
                           A, Bw, ldk, cm, cn, kn, tid);
            }
            asm volatile("cp.async.commit_group;" ::: "memory");
        }

        const uint32_t* As = (const uint32_t*)(smem + s * STAGE_BYTES);
        const uint32_t* Bs = (const uint32_t*)(smem + (NSTG + s) * STAGE_BYTES);
        #pragma unroll
        for (int ks = 0; ks < 4; ++ks) {
            const int k0 = ks * 8 + lk;
            uint32_t a[2][4];
            #pragma unroll
            for (int mi = 0; mi < 2; ++mi) {
                const int r = warpM * 32 + mi * 16 + la;
                a[mi][0] = As[r * STRIDE + k0];
                a[mi][1] = As[(r + 8) * STRIDE + k0];
                a[mi][2] = As[r * STRIDE + k0 + 4];
                a[mi][3] = As[(r + 8) * STRIDE + k0 + 4];
            }
            #pragma unroll
            for (int ni = 0; ni < 8; ++ni) {
                const int n = warpN * 64 + ni * 8 + la;
                const uint32_t b0 = Bs[n * STRIDE + k0];
                const uint32_t b1 = Bs[n * STRIDE + k0 + 4];
                mma1688(acc[0][ni], a[0], b0, b1);
                mma1688(acc[1][ni], a[1], b0, b1);
            }
        }
    }

    #pragma unroll
    for (int mi = 0; mi < 2; ++mi) {
        #pragma unroll
        for (int half = 0; half < 2; ++half) {
            const int row = cm + warpM * 32 + mi * 16 + la + half * 8;
            const long rb = (long)row * N;
            #pragma unroll
            for (int ni = 0; ni < 8; ++ni) {
                const int c = cn + warpN * 64 + ni * 8 + lk * 2;
                float v0 = acc[mi][ni][half * 2 + 0];
                float v1 = acc[mi][ni][half * 2 + 1];
                if (!(flags & FLAG_NOBIAS)) {
                    v0 += bias[c]; v1 += bias[c + 1];
                }
                if (flags & FLAG_GELU) {
                    v0 = 0.5f * v0 * (1.0f + erff(v0 * 0.70710678118654752f));
                    v1 = 0.5f * v1 * (1.0f + erff(v1 * 0.70710678118654752f));
                    v0 = rna_f(v0);
                    v1 = rna_f(v1);
                }
                if (flags & FLAG_RES) {
                    float2 r = *(const float2*)&Res[rb + c];
                    v0 += r.x; v1 += r.y;
                }
                float2 o; o.x = v0; o.y = v1;
                *(float2*)&C[rb + c] = o;
            }
        }
    }
}

// ---------------------------------------------------------------------------
// add3: out = s1 + s2 + bias (+res)   (split-K reduction)
// ---------------------------------------------------------------------------
__global__ void add3_kernel(const float4* __restrict__ s1, const float4* __restrict__ s2,
                            const float4* __restrict__ res, const float* __restrict__ bias,
                            float4* __restrict__ out, int Ncols, int n4, int useRes)
{
    int i = blockIdx.x * 256 + threadIdx.x;
    if (i >= n4) return;
    float4 a = s1[i], b = s2[i];
    int col = (i * 4) % Ncols;
    float4 v;
    v.x = a.x + b.x + bias[col];
    v.y = a.y + b.y + bias[col + 1];
    v.z = a.z + b.z + bias[col + 2];
    v.w = a.w + b.w + bias[col + 3];
    if (useRes) {
        float4 r = res[i];
        v.x += r.x; v.y += r.y; v.z += r.z; v.w += r.w;
    }
    out[i] = v;
}

// ---------------------------------------------------------------------------
// Fourier embed + input projection (rna output: feeds kv GEMM)
// ---------------------------------------------------------------------------
__global__ void embed_kernel(const float* __restrict__ pc,
                             const float* __restrict__ feats,
                             const float* __restrict__ inW,
                             const float* __restrict__ inb,
                             float* __restrict__ out)
{
    __shared__ float e[IN_DIM];
    const int row = blockIdx.x;
    const int t = threadIdx.x;
    if (t < IN_DIM) {
        float v;
        if (t < 3) {
            v = pc[row * 3 + t];
        } else if (t < 27) {
            int j = (t - 3) >> 3, f = (t - 3) & 7;
            v = sinf(pc[row * 3 + j] * (float)(1 << f));
        } else if (t < 51) {
            int j = (t - 27) >> 3, f = (t - 27) & 7;
            v = cosf(pc[row * 3 + j] * (float)(1 << f));
        } else {
            v = feats[row * 3 + (t - 51)];
        }
        e[t] = v;
    }
    __syncthreads();
    #pragma unroll
    for (int rep = 0; rep < 3; ++rep) {
        int o = t + rep * 256;
        const float* w = inW + o * IN_DIM;
        float s = inb[o];
        #pragma unroll
        for (int k = 0; k < IN_DIM; ++k) s = fmaf(w[k], e[k], s);
        out[(long)row * WIDTH + o] = rna_f(s);
    }
}

// ---------------------------------------------------------------------------
// LayerNorm (rna output: feeds qkv / fc GEMMs)
// ---------------------------------------------------------------------------
__global__ void ln_kernel(const float* __restrict__ X,
                          const float* __restrict__ s,
                          const float* __restrict__ b,
                          float* __restrict__ Y)
{
    const int row = blockIdx.x;
    const int t = threadIdx.x;
    const float* x = X + (long)row * WIDTH;
    float v0 = x[t], v1 = x[t + 256], v2 = x[t + 512];
    float sum = v0 + v1 + v2;
    float sq = v0 * v0 + v1 * v1 + v2 * v2;
    __shared__ float red[16];
    #pragma unroll
    for (int o = 16; o; o >>= 1) {
        sum += __shfl_xor_sync(0xffffffffu, sum, o);
        sq  += __shfl_xor_sync(0xffffffffu, sq,  o);
    }
    const int w = t >> 5, l = t & 31;
    if (l == 0) { red[w] = sum; red[w + 8] = sq; }
    __syncthreads();
    if (t < 32) {
        float a = (l < 8) ? red[l] : 0.f;
        float c = (l < 8) ? red[l + 8] : 0.f;
        #pragma unroll
        for (int o = 4; o; o >>= 1) {
            a += __shfl_xor_sync(0xffffffffu, a, o);
            c += __shfl_xor_sync(0xffffffffu, c, o);
        }
        if (l == 0) { red[0] = a; red[1] = c; }
    }
    __syncthreads();
    const float mu = red[0] * (1.f / WIDTH);
    const float var = red[1] * (1.f / WIDTH) - mu * mu;
    const float rs = rsqrtf(var + 1e-5f);
    float* y = Y + (long)row * WIDTH;
    y[t]       = rna_f((v0 - mu) * rs * s[t]       + b[t]);
    y[t + 256] = rna_f((v1 - mu) * rs * s[t + 256] + b[t + 256]);
    y[t + 512] = rna_f((v2 - mu) * rs * s[t + 512] + b[t + 512]);
}

// ---------------------------------------------------------------------------
// Flash attention fp32 SIMT (R13 version — measured best; rna output)
// ---------------------------------------------------------------------------
#define FLASH_SMEM ((2 * 128 * 65 + 2 * 64 * 65) * 4)

__global__ __launch_bounds__(256)
void flash_kernel(const float* __restrict__ Qp, const float* __restrict__ Kp,
                  const float* __restrict__ Vp, float* __restrict__ Op,
                  int Lk, int qRS, int kRS, int oRS,
                  long qBS, long kBS, long oBS,
                  int qHS, int kHS, int oHS)
{
    extern __shared__ float sm[];
    float* Qs = sm;
    float* Ps = sm + 128 * 65;
    float* Ks = sm + 2 * 128 * 65;
    float* Vs = Ks + 64 * 65;

    const int tid = threadIdx.x;
    const int tx = tid & 15;
    const int ty = tid >> 4;
    const int qt = blockIdx.x, h = blockIdx.y, b = blockIdx.z;

    const float* Q  = Qp + (long)b * qBS + h * qHS + (long)(qt * 128) * qRS;
    const float* Kb = Kp + (long)b * kBS + h * kHS;
    const float* Vb = Vp + (long)b * kBS + h * kHS;
    float*       O  = Op + (long)b * oBS + h * oHS + (long)(qt * 128) * oRS;

    for (int idx = tid; idx < 128 * 64; idx += 256) {
        int r = idx >> 6, d = idx & 63;
        Qs[r * 65 + d] = Q[(long)r * qRS + d];
    }

    float m[8], l[8], o[8][4];
    #pragma unroll
    for (int i = 0; i < 8; ++i) {
        m[i] = -3.0e38f; l[i] = 0.f;
        #pragma unroll
        for (int j = 0; j < 4; ++j) o[i][j] = 0.f;
    }
    __syncthreads();

    for (int c0 = 0; c0 < Lk; c0 += 64) {
        for (int idx = tid; idx < 64 * 64; idx += 256) {
            int r = idx >> 6, d = idx & 63;
            Ks[r * 65 + d] = Kb[(long)(c0 + r) * kRS + d];
            Vs[r * 65 + d] = Vb[(long)(c0 + r) * kRS + d];
        }
        __syncthreads();

        float s[8][4];
        #pragma unroll
        for (int i = 0; i < 8; ++i)
            #pragma unroll
            for (int j = 0; j < 4; ++j) s[i][j] = 0.f;
        #pragma unroll 16
        for (int d = 0; d < 64; ++d) {
            float a[8], bf[4];
            #pragma unroll
            for (int i = 0; i < 8; ++i) a[i] = Qs[(ty * 8 + i) * 65 + d];
            #pragma unroll
            for (int j = 0; j < 4; ++j) bf[j] = Ks[(tx * 4 + j) * 65 + d];
            #pragma unroll
            for (int i = 0; i < 8; ++i)
                #pragma unroll
                for (int j = 0; j < 4; ++j)
                    s[i][j] = fmaf(a[i], bf[j], s[i][j]);
        }

        #pragma unroll
        for (int i = 0; i < 8; ++i) {
            #pragma unroll
            for (int j = 0; j < 4; ++j) s[i][j] *= 0.125f;
            float mx = fmaxf(fmaxf(s[i][0], s[i][1]), fmaxf(s[i][2], s[i][3]));
            #pragma unroll
            for (int off = 1; off < 16; off <<= 1)
                mx = fmaxf(mx, __shfl_xor_sync(0xffffffffu, mx, off));
            const float mnew = fmaxf(m[i], mx);
            const float corr = __expf(m[i] - mnew);
            m[i] = mnew;
            float rsum = 0.f;
            #pragma unroll
            for (int j = 0; j < 4; ++j) {
                s[i][j] = __expf(s[i][j] - mnew);
                rsum += s[i][j];
            }
            #pragma unroll
            for (int off = 1; off < 16; off <<= 1)
                rsum += __shfl_xor_sync(0xffffffffu, rsum, off);
            l[i] = l[i] * corr + rsum;
            #pragma unroll
            for (int j = 0; j < 4; ++j) {
                o[i][j] *= corr;
                Ps[(ty * 8 + i) * 65 + tx * 4 + j] = s[i][j];
            }
        }
        __syncthreads();

        #pragma unroll 16
        for (int c = 0; c < 64; ++c) {
            float a[8], bf[4];
            #pragma unroll
            for (int i = 0; i < 8; ++i) a[i] = Ps[(ty * 8 + i) * 65 + c];
            #pragma unroll
            for (int j = 0; j < 4; ++j) bf[j] = Vs[c * 65 + tx * 4 + j];
            #pragma unroll
            for (int i = 0; i < 8; ++i)
                #pragma unroll
                for (int j = 0; j < 4; ++j)
                    o[i][j] = fmaf(a[i], bf[j], o[i][j]);
        }
        __syncthreads();
    }

    #pragma unroll
    for (int i = 0; i < 8; ++i) {
        const float inv = 1.f / l[i];
        const int r = ty * 8 + i;
        #pragma unroll
        for (int j = 0; j < 4; ++j)
            O[(long)r * oRS + tx * 4 + j] = rna_f(o[i][j] * inv);
    }
}

__global__ void copy_kernel(const float* __restrict__ src, float* __restrict__ dst, int n)
{
    int i = blockIdx.x * 256 + threadIdx.x;
    if (i < n) dst[i] = src[i];
}

// ---------------------------------------------------------------------------
// kernel_launch
// ---------------------------------------------------------------------------
extern "C" void kernel_launch(void* const* d_in, const int* in_sizes, int n_in,
                              void* d_out, int out_size)
{
    const float* pc       = (const float*)d_in[0];
    const float* feats    = (const float*)d_in[1];
    const float* query    = (const float*)d_in[2];
    const float* in_W     = (const float*)d_in[3];
    const float* in_b     = (const float*)d_in[4];
    const float* ca_qkv_W = (const float*)d_in[5];
    const float* ca_qkv_b = (const float*)d_in[6];
    const float* ca_proj_W= (const float*)d_in[7];
    const float* ca_proj_b= (const float*)d_in[8];
    const float* ln1_s    = (const float*)d_in[9];
    const float* ln1_b    = (const float*)d_in[10];
    const float* qkv_W    = (const float*)d_in[11];
    const float* qkv_b    = (const float*)d_in[12];
    const float* proj_W   = (const float*)d_in[13];
    const float* proj_b   = (const float*)d_in[14];
    const float* ln2_s    = (const float*)d_in[15];
    const float* ln2_b    = (const float*)d_in[16];
    const float* fc_W     = (const float*)d_in[17];
    const float* fc_b     = (const float*)d_in[18];
    const float* fc2_W    = (const float*)d_in[19];
    const float* fc2_b    = (const float*)d_in[20];

    float *data, *kv, *qb, *attn, *x, *h, *ffn, *wtf, *split;
    cudaGetSymbolAddress((void**)&data, g_data);
    cudaGetSymbolAddress((void**)&kv,   g_kv);
    cudaGetSymbolAddress((void**)&qb,   g_q);
    cudaGetSymbolAddress((void**)&attn, g_attn);
    cudaGetSymbolAddress((void**)&x,    g_x);
    cudaGetSymbolAddress((void**)&h,    g_h);
    cudaGetSymbolAddress((void**)&ffn,  g_ffn);
    cudaGetSymbolAddress((void**)&wtf,  g_wtf);
    cudaGetSymbolAddress((void**)&split, g_split);

    cudaFuncSetAttribute(flash_kernel, cudaFuncAttributeMaxDynamicSharedMemorySize,
                         FLASH_SMEM);
    cudaFuncSetAttribute(gemm_mma, cudaFuncAttributeMaxDynamicSharedMemorySize,
                         GEMM_SMEM);

    const int n4 = LAT_ROWS * WIDTH / 4;
    const int add_blocks = (n4 + 255) / 256;

    // 0) round all weights to tf32 (single fused launch)
    rna_all<<<(int)((R4_E5 + 255) / 256), 256>>>(
        ca_qkv_W, ca_proj_W, qkv_W, proj_W, fc_W, fc2_W, (float4*)wtf);

    // 1) fourier embed + input projection
    embed_kernel<<<BN_ROWS, 256>>>(pc, feats, in_W, in_b, data);

    // 2) kv = data @ ca_qkv_W[768:2304].T + b[768:]
    gemm_mma<<<dim3((2 * WIDTH) / 128, BN_ROWS / 128), 256, GEMM_SMEM>>>(
        data, wtf + W_CAQKV + (long)WIDTH * WIDTH, ca_qkv_b + WIDTH, nullptr, kv,
        BN_ROWS, 2 * WIDTH, WIDTH, WIDTH, 0);

    // 3) q = query @ ca_qkv_W[:768].T + b[:768]
    gemm_mma<<<dim3(WIDTH / 128, N_LAT / 128), 256, GEMM_SMEM>>>(
        query, wtf + W_CAQKV, ca_qkv_b, nullptr, qb, N_LAT, WIDTH, WIDTH, WIDTH, 0);

    // 4) cross attention (latents attend to 4096 points)
    flash_kernel<<<dim3(N_LAT / 128, HEADS, BATCH), 256, FLASH_SMEM>>>(
        qb, kv, kv + WIDTH, attn,
        NPTS, WIDTH, 2 * WIDTH, WIDTH,
        0L, (long)NPTS * 2 * WIDTH, (long)N_LAT * WIDTH,
        D_HEAD, D_HEAD, D_HEAD);

    // 5) latents = attn @ ca_proj_W.T + b   (split-K x2)
    gemm_mma<<<dim3(WIDTH / 128, LAT_ROWS / 128, 2), 256, GEMM_SMEM>>>(
        attn, wtf + W_CAPROJ, nullptr, nullptr, split,
        LAT_ROWS, WIDTH, WIDTH / 2, WIDTH, FLAG_NOBIAS);
    add3_kernel<<<add_blocks, 256>>>(
        (const float4*)split, (const float4*)(split + (long)LAT_ROWS * WIDTH),
        nullptr, ca_proj_b, (float4*)x, WIDTH, n4, 0);

    // 6) transformer blocks
    for (int L = 0; L < LAYERS; ++L) {
        ln_kernel<<<LAT_ROWS, 256>>>(x, ln1_s + L * WIDTH, ln1_b + L * WIDTH, h);

        float* qkvb = ffn;
        gemm_mma<<<dim3((3 * WIDTH) / 128, LAT_ROWS / 128), 256, GEMM_SMEM>>>(
            h, wtf + W_QKV + (long)L * 3 * WIDTH * WIDTH, qkv_b + (long)L * 3 * WIDTH,
            nullptr, qkvb, LAT_ROWS, 3 * WIDTH, WIDTH, WIDTH, 0);

        flash_kernel<<<dim3(N_LAT / 128, HEADS, BATCH), 256, FLASH_SMEM>>>(
            qkvb, qkvb + D_HEAD, qkvb + 2 * D_HEAD, attn,
            N_LAT, 3 * WIDTH, 3 * WIDTH, WIDTH,
            (long)N_LAT * 3 * WIDTH, (long)N_LAT * 3 * WIDTH, (long)N_LAT * WIDTH,
            3 * D_HEAD, 3 * D_HEAD, D_HEAD);

        // proj: split-K x2 + add (res = x)
        gemm_mma<<<dim3(WIDTH / 128, LAT_ROWS / 128, 2), 256, GEMM_SMEM>>>(
            attn, wtf + W_PROJ + (long)L * WIDTH * WIDTH, nullptr, nullptr, split,
            LAT_ROWS, WIDTH, WIDTH / 2, WIDTH, FLAG_NOBIAS);
        add3_kernel<<<add_blocks, 256>>>(
            (const float4*)split, (const float4*)(split + (long)LAT_ROWS * WIDTH),
            (const float4*)x, proj_b + (long)L * WIDTH, (float4*)x, WIDTH, n4, 1);

        ln_kernel<<<LAT_ROWS, 256>>>(x, ln2_s + L * WIDTH, ln2_b + L * WIDTH, h);

        gemm_mma<<<dim3((4 * WIDTH) / 128, LAT_ROWS / 128), 256, GEMM_SMEM>>>(
            h, wtf + W_FC + (long)L * 4 * WIDTH * WIDTH, fc_b + (long)L * 4 * WIDTH,
            nullptr, ffn, LAT_ROWS, 4 * WIDTH, WIDTH, WIDTH, FLAG_GELU);

        // fc2: split-K x2 + add (res = x)
        float* Cout = (L == LAYERS - 1) ? (float*)d_out : x;
        gemm_mma<<<dim3(WIDTH / 128, LAT_ROWS / 128, 2), 256, GEMM_SMEM>>>(
            ffn, wtf + W_FC2 + (long)L * WIDTH * 4 * WIDTH, nullptr, nullptr, split,
            LAT_ROWS, WIDTH, 2 * WIDTH, 4 * WIDTH, FLAG_NOBIAS);
        add3_kernel<<<add_blocks, 256>>>(
            (const float4*)split, (const float4*)(split + (long)LAT_ROWS * WIDTH),
            (const float4*)x, fc2_b + (long)L * WIDTH, (float4*)Cout, WIDTH, n4, 1);
    }

    // 7) pc passthrough if output holds both
    const int lat_elems = LAT_ROWS * WIDTH;
    const int pc_elems = BATCH * NPTS * 3;
    if (out_size >= lat_elems + pc_elems) {
        copy_kernel<<<(pc_elems + 255) / 256, 256>>>(
            pc, (float*)d_out + lat_elems, pc_elems);
    }
}